// round 6
// baseline (speedup 1.0000x reference)
#include <cuda_runtime.h>
#include <cuda_bf16.h>
#include <cstdint>

// MMDLayer via mma.sync bf16 (HMMA) with 2-way bf16 split (3 passes) for accuracy.
// out[t,s] = (1 - (||x_t||^2 + ||C_k||^2 - 2 x_t.C_k)/128)^3,  k = 511+t-s
// C[k] = init[511-k] (k<512) else x[k-512].
// Per CTA: D[64 x 64] = A.B^T over K=128; 8 warps, warp tile 32x16.

#define T_LEN 2048
#define S_LEN 512
#define DIM   128
#define BT    64
#define BK    64
#define NKT   9
#define NTHR  256
#define PITCH 272                     // bytes per tile row: 256B data + 16B pad

#define TSZ    (64 * PITCH)           // 17408 B per tile
#define OFF_AH 0
#define OFF_AL (OFF_AH + TSZ)
#define OFF_BH (OFF_AL + TSZ)
#define OFF_BL (OFF_BH + TSZ)
#define OFF_NA (OFF_BL + TSZ)
#define OFF_NB (OFF_NA + 64 * 4)
#define SMEM_TOTAL (OFF_NB + 64 * 4)  // ~70.2 KB

__device__ __forceinline__ uint32_t smem_u32(const void* p) {
    uint32_t a;
    asm("{ .reg .u64 t; cvta.to.shared.u64 t, %1; cvt.u32.u64 %0, t; }" : "=r"(a) : "l"(p));
    return a;
}

__device__ __forceinline__ void ldsm4(uint32_t r[4], uint32_t addr) {
    asm volatile("ldmatrix.sync.aligned.m8n8.x4.shared.b16 {%0,%1,%2,%3}, [%4];"
                 : "=r"(r[0]), "=r"(r[1]), "=r"(r[2]), "=r"(r[3]) : "r"(addr));
}

__device__ __forceinline__ void mma16816(float c[4], const uint32_t a[4],
                                         uint32_t b0, uint32_t b1) {
    asm volatile(
        "mma.sync.aligned.m16n8k16.row.col.f32.bf16.bf16.f32 "
        "{%0,%1,%2,%3}, {%4,%5,%6,%7}, {%8,%9}, {%0,%1,%2,%3};"
        : "+f"(c[0]), "+f"(c[1]), "+f"(c[2]), "+f"(c[3])
        : "r"(a[0]), "r"(a[1]), "r"(a[2]), "r"(a[3]), "r"(b0), "r"(b1));
}

__device__ __forceinline__ unsigned short us(__nv_bfloat16 h) {
    return __bfloat16_as_ushort(h);
}

__global__ __launch_bounds__(NTHR, 2)
void mmd_mma_kernel(const float* __restrict__ x,
                    const float* __restrict__ init,
                    float* __restrict__ out)
{
    extern __shared__ char sm[];
    const uint32_t smb = smem_u32(sm);
    const int tid  = threadIdx.x;
    const int wid  = tid >> 5;
    const int lane = tid & 31;
    const int bx = blockIdx.x;
    const int t0 = blockIdx.y * BT;
    const int k0 = t0 + BK * bx;

    float* nA = (float*)(sm + OFF_NA);
    float* nB = (float*)(sm + OFF_NB);

    // ---- Prologue: one row per warp-iteration; load, split hi/lo bf16, norm ----
    for (int r = wid; r < BT + BK; r += 8) {
        const bool isA = r < BT;
        const int row  = isA ? r : r - BT;
        const float* src;
        if (isA) {
            src = x + (size_t)(t0 + row) * DIM;
        } else {
            const int k = k0 + row;   // k0+63 <= 2559 always in range
            src = (k < S_LEN) ? init + (size_t)(S_LEN - 1 - k) * DIM
                              : x    + (size_t)(k - S_LEN) * DIM;
        }
        const float4 v = reinterpret_cast<const float4*>(src)[lane];

        __nv_bfloat16 h0 = __float2bfloat16_rn(v.x);
        __nv_bfloat16 h1 = __float2bfloat16_rn(v.y);
        __nv_bfloat16 h2 = __float2bfloat16_rn(v.z);
        __nv_bfloat16 h3 = __float2bfloat16_rn(v.w);
        __nv_bfloat16 l0 = __float2bfloat16_rn(v.x - __bfloat162float(h0));
        __nv_bfloat16 l1 = __float2bfloat16_rn(v.y - __bfloat162float(h1));
        __nv_bfloat16 l2 = __float2bfloat16_rn(v.z - __bfloat162float(h2));
        __nv_bfloat16 l3 = __float2bfloat16_rn(v.w - __bfloat162float(h3));

        uint2 H = make_uint2((uint32_t)us(h0) | ((uint32_t)us(h1) << 16),
                             (uint32_t)us(h2) | ((uint32_t)us(h3) << 16));
        uint2 L = make_uint2((uint32_t)us(l0) | ((uint32_t)us(l1) << 16),
                             (uint32_t)us(l2) | ((uint32_t)us(l3) << 16));

        char* hb = sm + (isA ? OFF_AH : OFF_BH) + row * PITCH + lane * 8;
        *reinterpret_cast<uint2*>(hb)       = H;
        *reinterpret_cast<uint2*>(hb + TSZ) = L;      // lo tile is +TSZ for both A,B

        float p = v.x * v.x + v.y * v.y + v.z * v.z + v.w * v.w;
        #pragma unroll
        for (int o = 16; o; o >>= 1) p += __shfl_xor_sync(0xFFFFFFFFu, p, o);
        if (lane == 0) (isA ? nA : nB)[row] = p;
    }
    __syncthreads();

    // ---- Warp tiling: 2 warps in M (32 rows each), 4 warps in N (16 cols each) ----
    const int wm = wid & 1;
    const int wn = wid >> 1;

    // ldmatrix per-lane addresses
    const int arow = wm * 32 + (lane & 7) + ((lane >> 3) & 1) * 8;
    const int acol = (lane >> 4) * 8;
    const uint32_t aH0 = smb + OFF_AH + (uint32_t)(arow * PITCH + acol * 2);
    const uint32_t aH1 = aH0 + 16 * PITCH;
    const int brow = wn * 16 + (lane & 7) + (lane >> 4) * 8;
    const int bcol = ((lane >> 3) & 1) * 8;
    const uint32_t bH = smb + OFF_BH + (uint32_t)(brow * PITCH + bcol * 2);

    float acc[2][2][4];
    #pragma unroll
    for (int i = 0; i < 2; i++)
        #pragma unroll
        for (int j = 0; j < 2; j++)
            #pragma unroll
            for (int q = 0; q < 4; q++)
                acc[i][j][q] = 0.f;

    // ---- Main loop: 8 K-steps of 16; passes hh + hl + lh into same accumulators ----
    #pragma unroll
    for (int ks = 0; ks < 8; ks++) {
        const uint32_t kb = (uint32_t)(ks * 32);    // 16 bf16 = 32 bytes
        uint32_t ah0[4], ah1[4], al0[4], al1[4], bh[4], bl[4];
        ldsm4(ah0, aH0 + kb);
        ldsm4(ah1, aH1 + kb);
        ldsm4(al0, aH0 + TSZ + kb);
        ldsm4(al1, aH1 + TSZ + kb);
        ldsm4(bh,  bH + kb);
        ldsm4(bl,  bH + TSZ + kb);

        // hh
        mma16816(acc[0][0], ah0, bh[0], bh[1]);
        mma16816(acc[0][1], ah0, bh[2], bh[3]);
        mma16816(acc[1][0], ah1, bh[0], bh[1]);
        mma16816(acc[1][1], ah1, bh[2], bh[3]);
        // hl
        mma16816(acc[0][0], ah0, bl[0], bl[1]);
        mma16816(acc[0][1], ah0, bl[2], bl[3]);
        mma16816(acc[1][0], ah1, bl[0], bl[1]);
        mma16816(acc[1][1], ah1, bl[2], bl[3]);
        // lh
        mma16816(acc[0][0], al0, bh[0], bh[1]);
        mma16816(acc[0][1], al0, bh[2], bh[3]);
        mma16816(acc[1][0], al1, bh[0], bh[1]);
        mma16816(acc[1][1], al1, bh[2], bh[3]);
    }

    // ---- Epilogue: d2 = nA + nB - 2*dot; out[t, 511+t-k] = (1 - d2/128)^3 ----
    #pragma unroll
    for (int mt = 0; mt < 2; mt++) {
        const int m  = wm * 32 + mt * 16 + (lane >> 2);
        const float na0 = nA[m];
        const float na1 = nA[m + 8];
        const int ta = t0 + m;
        const int tb = ta + 8;
        #pragma unroll
        for (int nt = 0; nt < 2; nt++) {
            const int n  = wn * 16 + nt * 8 + 2 * (lane & 3);
            const int k  = k0 + n;
            const float nb0 = nB[n];
            const float nb1 = nB[n + 1];
            const float* a4 = acc[mt][nt];

            const int sa = 511 + ta - k;   // for (ta, k); (ta,k+1) -> sa-1
            const int sb = 511 + tb - k;

            float d2, u;
            if (sa >= 0 && sa < S_LEN) {
                d2 = na0 + nb0 - 2.0f * a4[0];
                u  = 1.0f - d2 * (1.0f / 128.0f);
                out[(size_t)ta * S_LEN + sa] = u * u * u;
            }
            if (sa - 1 >= 0 && sa - 1 < S_LEN) {
                d2 = na0 + nb1 - 2.0f * a4[1];
                u  = 1.0f - d2 * (1.0f / 128.0f);
                out[(size_t)ta * S_LEN + sa - 1] = u * u * u;
            }
            if (sb >= 0 && sb < S_LEN) {
                d2 = na1 + nb0 - 2.0f * a4[2];
                u  = 1.0f - d2 * (1.0f / 128.0f);
                out[(size_t)tb * S_LEN + sb] = u * u * u;
            }
            if (sb - 1 >= 0 && sb - 1 < S_LEN) {
                d2 = na1 + nb1 - 2.0f * a4[3];
                u  = 1.0f - d2 * (1.0f / 128.0f);
                out[(size_t)tb * S_LEN + sb - 1] = u * u * u;
            }
        }
    }
}

extern "C" void kernel_launch(void* const* d_in, const int* in_sizes, int n_in,
                              void* d_out, int out_size)
{
    const float* x    = (const float*)d_in[0];   // (1, 2048, 1, 128) fp32
    const float* init = (const float*)d_in[1];   // (512, 128) fp32
    float* out = (float*)d_out;                  // (1, 2048, 512) fp32

    cudaFuncSetAttribute(mmd_mma_kernel,
                         cudaFuncAttributeMaxDynamicSharedMemorySize, SMEM_TOTAL);
    dim3 grid(NKT, T_LEN / BT);                  // (9, 32) = 288 CTAs, 2/SM, one wave
    mmd_mma_kernel<<<grid, NTHR, SMEM_TOTAL>>>(x, init, out);
}

// round 7
// speedup vs baseline: 1.1324x; 1.1324x over previous
#include <cuda_runtime.h>
#include <cuda_bf16.h>
#include <cstdint>

// MMDLayer via mma.sync bf16 (HMMA), 2-way bf16 split (3 passes: hh+hl+lh).
// out[t,s] = (1 - (||x_t||^2 + ||C_k||^2 - 2 x_t.C_k)/128)^3,  k = 511+t-s
// C[k] = init[511-k] (k<512) else x[k-512].
// Per CTA: D[32 x 64] = A.B^T over K=128; 8 warps (2M x 4N), warp tile 16x16.
// 4 CTAs/SM for latency hiding (prologue LDG+SHFL chains overlap across CTAs).

#define T_LEN 2048
#define S_LEN 512
#define DIM   128
#define BT    32
#define BK    64
#define NKT   9
#define NTHR  256
#define PITCH 272                     // bytes per tile row: 256B data + 16B pad

#define ASZ    (BT * PITCH)           // 8704
#define BSZ    (BK * PITCH)           // 17408
#define OFF_AH 0
#define OFF_AL (OFF_AH + ASZ)
#define OFF_BH (OFF_AL + ASZ)
#define OFF_BL (OFF_BH + BSZ)
#define OFF_NA (OFF_BL + BSZ)
#define OFF_NB (OFF_NA + BT * 4)
#define SMEM_TOTAL (OFF_NB + BK * 4)  // 52608 B -> 4 CTAs/SM

__device__ __forceinline__ uint32_t smem_u32(const void* p) {
    uint32_t a;
    asm("{ .reg .u64 t; cvta.to.shared.u64 t, %1; cvt.u32.u64 %0, t; }" : "=r"(a) : "l"(p));
    return a;
}

__device__ __forceinline__ void ldsm4(uint32_t r[4], uint32_t addr) {
    asm volatile("ldmatrix.sync.aligned.m8n8.x4.shared.b16 {%0,%1,%2,%3}, [%4];"
                 : "=r"(r[0]), "=r"(r[1]), "=r"(r[2]), "=r"(r[3]) : "r"(addr));
}

__device__ __forceinline__ void mma16816(float c[4], const uint32_t a[4],
                                         uint32_t b0, uint32_t b1) {
    asm volatile(
        "mma.sync.aligned.m16n8k16.row.col.f32.bf16.bf16.f32 "
        "{%0,%1,%2,%3}, {%4,%5,%6,%7}, {%8,%9}, {%0,%1,%2,%3};"
        : "+f"(c[0]), "+f"(c[1]), "+f"(c[2]), "+f"(c[3])
        : "r"(a[0]), "r"(a[1]), "r"(a[2]), "r"(a[3]), "r"(b0), "r"(b1));
}

__device__ __forceinline__ unsigned short us(__nv_bfloat16 h) {
    return __bfloat16_as_ushort(h);
}

// Load one fp32 row (128 vals, one float4 per lane), split hi/lo bf16 into smem,
// warp-reduce the squared norm, write it to nrm[row].
__device__ __forceinline__ void load_split_row(const float* __restrict__ src,
                                               char* hb, float* nrm_slot, int lane)
{
    const float4 v = reinterpret_cast<const float4*>(src)[lane];
    __nv_bfloat16 h0 = __float2bfloat16_rn(v.x);
    __nv_bfloat16 h1 = __float2bfloat16_rn(v.y);
    __nv_bfloat16 h2 = __float2bfloat16_rn(v.z);
    __nv_bfloat16 h3 = __float2bfloat16_rn(v.w);
    __nv_bfloat16 l0 = __float2bfloat16_rn(v.x - __bfloat162float(h0));
    __nv_bfloat16 l1 = __float2bfloat16_rn(v.y - __bfloat162float(h1));
    __nv_bfloat16 l2 = __float2bfloat16_rn(v.z - __bfloat162float(h2));
    __nv_bfloat16 l3 = __float2bfloat16_rn(v.w - __bfloat162float(h3));
    uint2 H = make_uint2((uint32_t)us(h0) | ((uint32_t)us(h1) << 16),
                         (uint32_t)us(h2) | ((uint32_t)us(h3) << 16));
    uint2 L = make_uint2((uint32_t)us(l0) | ((uint32_t)us(l1) << 16),
                         (uint32_t)us(l2) | ((uint32_t)us(l3) << 16));
    *reinterpret_cast<uint2*>(hb)       = H;
    *reinterpret_cast<uint2*>(hb + ASZ) = L;      // lo tile sits +ASZ (A) / +BSZ (B): see call sites
    float p = v.x * v.x + v.y * v.y + v.z * v.z + v.w * v.w;
    #pragma unroll
    for (int o = 16; o; o >>= 1) p += __shfl_xor_sync(0xFFFFFFFFu, p, o);
    if (lane == 0) *nrm_slot = p;
}

__global__ __launch_bounds__(NTHR, 4)
void mmd_mma_kernel(const float* __restrict__ x,
                    const float* __restrict__ init,
                    float* __restrict__ out)
{
    extern __shared__ char sm[];
    const uint32_t smb = smem_u32(sm);
    const int tid  = threadIdx.x;
    const int wid  = tid >> 5;
    const int lane = tid & 31;
    const int bx = blockIdx.x;
    const int t0 = blockIdx.y * BT;
    const int k0 = t0 + BK * bx;

    float* nA = (float*)(sm + OFF_NA);
    float* nB = (float*)(sm + OFF_NB);

    // ---- Prologue: A rows (4 iters/warp), B rows (8 iters/warp), unrolled ----
    {
        const int r = wid; // A: rows wid, wid+8, wid+16, wid+24
        #pragma unroll
        for (int it = 0; it < 4; it++) {
            const int row = r + 8 * it;
            load_split_row(x + (size_t)(t0 + row) * DIM,
                           sm + OFF_AH + row * PITCH + lane * 8, nA + row, lane);
        }
    }
    {
        #pragma unroll
        for (int it = 0; it < 8; it++) {
            const int row = wid + 8 * it;
            int k = k0 + row;
            if (k > T_LEN + S_LEN - 1) k = T_LEN + S_LEN - 1;  // clamped rows masked later
            const float* src = (k < S_LEN) ? init + (size_t)(S_LEN - 1 - k) * DIM
                                           : x    + (size_t)(k - S_LEN) * DIM;
            // NOTE: lo tile for B sits at +BSZ, so write directly:
            const float4 v = reinterpret_cast<const float4*>(src)[lane];
            __nv_bfloat16 h0 = __float2bfloat16_rn(v.x);
            __nv_bfloat16 h1 = __float2bfloat16_rn(v.y);
            __nv_bfloat16 h2 = __float2bfloat16_rn(v.z);
            __nv_bfloat16 h3 = __float2bfloat16_rn(v.w);
            __nv_bfloat16 l0 = __float2bfloat16_rn(v.x - __bfloat162float(h0));
            __nv_bfloat16 l1 = __float2bfloat16_rn(v.y - __bfloat162float(h1));
            __nv_bfloat16 l2 = __float2bfloat16_rn(v.z - __bfloat162float(h2));
            __nv_bfloat16 l3 = __float2bfloat16_rn(v.w - __bfloat162float(h3));
            uint2 H = make_uint2((uint32_t)us(h0) | ((uint32_t)us(h1) << 16),
                                 (uint32_t)us(h2) | ((uint32_t)us(h3) << 16));
            uint2 L = make_uint2((uint32_t)us(l0) | ((uint32_t)us(l1) << 16),
                                 (uint32_t)us(l2) | ((uint32_t)us(l3) << 16));
            char* hb = sm + OFF_BH + row * PITCH + lane * 8;
            *reinterpret_cast<uint2*>(hb)       = H;
            *reinterpret_cast<uint2*>(hb + BSZ) = L;
            float p = v.x * v.x + v.y * v.y + v.z * v.z + v.w * v.w;
            #pragma unroll
            for (int o = 16; o; o >>= 1) p += __shfl_xor_sync(0xFFFFFFFFu, p, o);
            if (lane == 0) nB[row] = p;
        }
    }
    __syncthreads();

    // ---- Warp tiling: 2 warps in M (16 rows each), 4 warps in N (16 cols each) ----
    const int wm = wid & 1;
    const int wn = wid >> 1;

    const int arow = wm * 16 + (lane & 7) + ((lane >> 3) & 1) * 8;
    const int acol = (lane >> 4) * 8;
    const uint32_t aH = smb + OFF_AH + (uint32_t)(arow * PITCH + acol * 2);
    const int brow = wn * 16 + (lane & 7) + (lane >> 4) * 8;
    const int bcol = ((lane >> 3) & 1) * 8;
    const uint32_t bH = smb + OFF_BH + (uint32_t)(brow * PITCH + bcol * 2);

    float acc[2][4];
    #pragma unroll
    for (int j = 0; j < 2; j++)
        #pragma unroll
        for (int q = 0; q < 4; q++)
            acc[j][q] = 0.f;

    // ---- Main loop: 8 K-steps of 16; hh + hl + lh into same accumulators ----
    #pragma unroll
    for (int ks = 0; ks < 8; ks++) {
        const uint32_t kb = (uint32_t)(ks * 32);
        uint32_t ah[4], al[4], bh[4], bl[4];
        ldsm4(ah, aH + kb);
        ldsm4(al, aH + ASZ + kb);
        ldsm4(bh, bH + kb);
        ldsm4(bl, bH + BSZ + kb);

        mma16816(acc[0], ah, bh[0], bh[1]);   // hh
        mma16816(acc[1], ah, bh[2], bh[3]);
        mma16816(acc[0], ah, bl[0], bl[1]);   // hl
        mma16816(acc[1], ah, bl[2], bl[3]);
        mma16816(acc[0], al, bh[0], bh[1]);   // lh
        mma16816(acc[1], al, bh[2], bh[3]);
    }

    // ---- Epilogue: d2 = nA + nB - 2*dot; out[t, 511+t-k] = (1 - d2/128)^3 ----
    const int m0 = wm * 16 + (lane >> 2);
    const int m1 = m0 + 8;
    const float na0 = nA[m0];
    const float na1 = nA[m1];
    const int ta = t0 + m0;
    const int tb = t0 + m1;
    #pragma unroll
    for (int nt = 0; nt < 2; nt++) {
        const int n  = wn * 16 + nt * 8 + 2 * (lane & 3);
        const int k  = k0 + n;
        const float nb0 = nB[n];
        const float nb1 = nB[n + 1];
        const float* a4 = acc[nt];

        const int sa = 511 + ta - k;
        const int sb = 511 + tb - k;
        float d2, u;
        if (sa >= 0 && sa < S_LEN) {
            d2 = na0 + nb0 - 2.0f * a4[0];
            u  = 1.0f - d2 * (1.0f / 128.0f);
            out[(size_t)ta * S_LEN + sa] = u * u * u;
        }
        if ((unsigned)(sa - 1) < S_LEN) {
            d2 = na0 + nb1 - 2.0f * a4[1];
            u  = 1.0f - d2 * (1.0f / 128.0f);
            out[(size_t)ta * S_LEN + sa - 1] = u * u * u;
        }
        if (sb >= 0 && sb < S_LEN) {
            d2 = na1 + nb0 - 2.0f * a4[2];
            u  = 1.0f - d2 * (1.0f / 128.0f);
            out[(size_t)tb * S_LEN + sb] = u * u * u;
        }
        if ((unsigned)(sb - 1) < S_LEN) {
            d2 = na1 + nb1 - 2.0f * a4[3];
            u  = 1.0f - d2 * (1.0f / 128.0f);
            out[(size_t)tb * S_LEN + sb - 1] = u * u * u;
        }
    }
}

extern "C" void kernel_launch(void* const* d_in, const int* in_sizes, int n_in,
                              void* d_out, int out_size)
{
    const float* x    = (const float*)d_in[0];   // (1, 2048, 1, 128) fp32
    const float* init = (const float*)d_in[1];   // (512, 128) fp32
    float* out = (float*)d_out;                  // (1, 2048, 512) fp32

    cudaFuncSetAttribute(mmd_mma_kernel,
                         cudaFuncAttributeMaxDynamicSharedMemorySize, SMEM_TOTAL);
    dim3 grid(NKT, T_LEN / BT);                  // (9, 64) = 576 CTAs, 4/SM, one wave
    mmd_mma_kernel<<<grid, NTHR, SMEM_TOTAL>>>(x, init, out);
}

// round 8
// speedup vs baseline: 1.1579x; 1.0226x over previous
#include <cuda_runtime.h>
#include <cuda_bf16.h>
#include <cstdint>

// MMDLayer via mma.sync bf16 (HMMA), 2-way bf16 split (hh+hl+lh).
// out[t,s] = (1 - (||x_t||^2 + ||C_k||^2 - 2 x_t.C_k)/128)^3,  k = 511+t-s
// C[k] = init[511-k] (k<512) else x[k-512];  A row t == C[512+t].
// Kernel 1 (prep): split all 2560 C rows into bf16 hi/lo scratch + fp32 norms.
// Kernel 2 (main): cp.async tiles from scratch, HMMA, epilogue. D[32x64]/CTA.

#define T_LEN 2048
#define S_LEN 512
#define DIM   128
#define NROWS 2560                    // virtual C rows
#define BT    32
#define BK    64
#define NKT   9
#define NTHR  256
#define PITCH 272                     // smem bytes per tile row (256B data + 16B pad)

#define ASZ    (BT * PITCH)           // 8704
#define BSZ    (BK * PITCH)           // 17408
#define OFF_AH 0
#define OFF_AL (OFF_AH + ASZ)
#define OFF_BH (OFF_AL + ASZ)
#define OFF_BL (OFF_BH + BSZ)
#define SMEM_TOTAL (OFF_BL + BSZ)     // 52224 B -> 4 CTAs/SM

// ---- global scratch (device globals: allocation-free) ----
__device__ __align__(256) unsigned short g_hi[NROWS * DIM];
__device__ __align__(256) unsigned short g_lo[NROWS * DIM];
__device__ __align__(256) float          g_nrm[NROWS];

__device__ __forceinline__ uint32_t smem_u32(const void* p) {
    uint32_t a;
    asm("{ .reg .u64 t; cvta.to.shared.u64 t, %1; cvt.u32.u64 %0, t; }" : "=r"(a) : "l"(p));
    return a;
}
__device__ __forceinline__ void ldsm4(uint32_t r[4], uint32_t addr) {
    asm volatile("ldmatrix.sync.aligned.m8n8.x4.shared.b16 {%0,%1,%2,%3}, [%4];"
                 : "=r"(r[0]), "=r"(r[1]), "=r"(r[2]), "=r"(r[3]) : "r"(addr));
}
__device__ __forceinline__ void mma16816(float c[4], const uint32_t a[4],
                                         uint32_t b0, uint32_t b1) {
    asm volatile(
        "mma.sync.aligned.m16n8k16.row.col.f32.bf16.bf16.f32 "
        "{%0,%1,%2,%3}, {%4,%5,%6,%7}, {%8,%9}, {%0,%1,%2,%3};"
        : "+f"(c[0]), "+f"(c[1]), "+f"(c[2]), "+f"(c[3])
        : "r"(a[0]), "r"(a[1]), "r"(a[2]), "r"(a[3]), "r"(b0), "r"(b1));
}
__device__ __forceinline__ void cp16(uint32_t dst, const void* src) {
    asm volatile("cp.async.cg.shared.global [%0], [%1], 16;"
                 :: "r"(dst), "l"(src) : "memory");
}
__device__ __forceinline__ unsigned short us(__nv_bfloat16 h) {
    return __bfloat16_as_ushort(h);
}

// ---- Kernel 1: split rows into hi/lo bf16 + norms (one warp per row) ----
__global__ __launch_bounds__(NTHR)
void prep_kernel(const float* __restrict__ x, const float* __restrict__ init)
{
    const int wid  = threadIdx.x >> 5;
    const int lane = threadIdx.x & 31;
    const int row  = blockIdx.x * 8 + wid;          // grid = 320 -> rows 0..2559

    const float* src = (row < S_LEN) ? init + (size_t)(S_LEN - 1 - row) * DIM
                                     : x    + (size_t)(row - S_LEN) * DIM;
    const float4 v = reinterpret_cast<const float4*>(src)[lane];

    __nv_bfloat16 h0 = __float2bfloat16_rn(v.x);
    __nv_bfloat16 h1 = __float2bfloat16_rn(v.y);
    __nv_bfloat16 h2 = __float2bfloat16_rn(v.z);
    __nv_bfloat16 h3 = __float2bfloat16_rn(v.w);
    __nv_bfloat16 l0 = __float2bfloat16_rn(v.x - __bfloat162float(h0));
    __nv_bfloat16 l1 = __float2bfloat16_rn(v.y - __bfloat162float(h1));
    __nv_bfloat16 l2 = __float2bfloat16_rn(v.z - __bfloat162float(h2));
    __nv_bfloat16 l3 = __float2bfloat16_rn(v.w - __bfloat162float(h3));

    uint2 H = make_uint2((uint32_t)us(h0) | ((uint32_t)us(h1) << 16),
                         (uint32_t)us(h2) | ((uint32_t)us(h3) << 16));
    uint2 L = make_uint2((uint32_t)us(l0) | ((uint32_t)us(l1) << 16),
                         (uint32_t)us(l2) | ((uint32_t)us(l3) << 16));
    reinterpret_cast<uint2*>(g_hi + (size_t)row * DIM)[lane] = H;
    reinterpret_cast<uint2*>(g_lo + (size_t)row * DIM)[lane] = L;

    float p = v.x * v.x + v.y * v.y + v.z * v.z + v.w * v.w;
    #pragma unroll
    for (int o = 16; o; o >>= 1) p += __shfl_xor_sync(0xFFFFFFFFu, p, o);
    if (lane == 0) g_nrm[row] = p;
}

// ---- Kernel 2: banded HMMA GEMM + epilogue ----
__global__ __launch_bounds__(NTHR, 4)
void mmd_mma_kernel(float* __restrict__ out)
{
    extern __shared__ char sm[];
    const uint32_t smb = smem_u32(sm);
    const int tid  = threadIdx.x;
    const int wid  = tid >> 5;
    const int lane = tid & 31;
    const int bx = blockIdx.x;
    const int t0 = blockIdx.y * BT;
    const int k0 = t0 + BK * bx;

    const int half = lane >> 4;        // 0: hi, 1: lo
    const int li   = lane & 15;        // 16B chunk index within row

    // ---- A tile: rows C[512+t0+r], r = wid + 8*it ----
    #pragma unroll
    for (int it = 0; it < 4; it++) {
        const int r = wid + 8 * it;
        const size_t g = (size_t)(S_LEN + t0 + r) * DIM + li * 8;
        const unsigned short* src = half ? (g_lo + g) : (g_hi + g);
        cp16(smb + (half ? OFF_AL : OFF_AH) + (uint32_t)(r * PITCH + li * 16), src);
    }
    // ---- B tile: rows C[k0+r], clamped (clamped rows masked in epilogue) ----
    #pragma unroll
    for (int it = 0; it < 8; it++) {
        const int r = wid + 8 * it;
        int k = k0 + r;
        if (k > NROWS - 1) k = NROWS - 1;
        const size_t g = (size_t)k * DIM + li * 8;
        const unsigned short* src = half ? (g_lo + g) : (g_hi + g);
        cp16(smb + (half ? OFF_BL : OFF_BH) + (uint32_t)(r * PITCH + li * 16), src);
    }
    asm volatile("cp.async.commit_group;" ::: "memory");

    // ---- Prefetch epilogue norms while cp.async is in flight ----
    const int wm = wid & 1;
    const int wn = wid >> 1;
    const int m0 = wm * 16 + (lane >> 2);
    const int m1 = m0 + 8;
    const int ta = t0 + m0;
    const int tb = t0 + m1;
    const int nbase = wn * 16 + 2 * (lane & 3);
    const float na0 = g_nrm[S_LEN + ta];
    const float na1 = g_nrm[S_LEN + tb];
    float nb[2][2];
    #pragma unroll
    for (int nt = 0; nt < 2; nt++) {
        int kk0 = k0 + nbase + nt * 8;
        int kk1 = kk0 + 1;
        nb[nt][0] = g_nrm[kk0 > NROWS - 1 ? NROWS - 1 : kk0];
        nb[nt][1] = g_nrm[kk1 > NROWS - 1 ? NROWS - 1 : kk1];
    }

    asm volatile("cp.async.wait_group 0;" ::: "memory");
    __syncthreads();

    // ---- ldmatrix addresses (16x16 warp tile; 2 warps M x 4 warps N) ----
    const int arow = wm * 16 + (lane & 7) + ((lane >> 3) & 1) * 8;
    const int acol = (lane >> 4) * 8;
    const uint32_t aH = smb + OFF_AH + (uint32_t)(arow * PITCH + acol * 2);
    const int brow = wn * 16 + (lane & 7) + (lane >> 4) * 8;
    const int bcol = ((lane >> 3) & 1) * 8;
    const uint32_t bH = smb + OFF_BH + (uint32_t)(brow * PITCH + bcol * 2);

    float acc[2][4];
    #pragma unroll
    for (int j = 0; j < 2; j++)
        #pragma unroll
        for (int q = 0; q < 4; q++)
            acc[j][q] = 0.f;

    // ---- Main loop: 8 K-steps of 16; hh + hl + lh ----
    #pragma unroll
    for (int ks = 0; ks < 8; ks++) {
        const uint32_t kb = (uint32_t)(ks * 32);
        uint32_t ah[4], al[4], bh[4], bl[4];
        ldsm4(ah, aH + kb);
        ldsm4(al, aH + ASZ + kb);
        ldsm4(bh, bH + kb);
        ldsm4(bl, bH + BSZ + kb);

        mma16816(acc[0], ah, bh[0], bh[1]);
        mma16816(acc[1], ah, bh[2], bh[3]);
        mma16816(acc[0], ah, bl[0], bl[1]);
        mma16816(acc[1], ah, bl[2], bl[3]);
        mma16816(acc[0], al, bh[0], bh[1]);
        mma16816(acc[1], al, bh[2], bh[3]);
    }

    // ---- Epilogue: d2 = nA + nB - 2*dot; out[t, 511+t-k] = (1 - d2/128)^3 ----
    #pragma unroll
    for (int nt = 0; nt < 2; nt++) {
        const int n  = nbase + nt * 8;
        const int k  = k0 + n;
        const float* a4 = acc[nt];

        const int sa = 511 + ta - k;
        const int sb = 511 + tb - k;
        float d2, u;
        if (sa >= 0 && sa < S_LEN) {
            d2 = na0 + nb[nt][0] - 2.0f * a4[0];
            u  = 1.0f - d2 * (1.0f / 128.0f);
            out[(size_t)ta * S_LEN + sa] = u * u * u;
        }
        if ((unsigned)(sa - 1) < S_LEN) {
            d2 = na0 + nb[nt][1] - 2.0f * a4[1];
            u  = 1.0f - d2 * (1.0f / 128.0f);
            out[(size_t)ta * S_LEN + sa - 1] = u * u * u;
        }
        if (sb >= 0 && sb < S_LEN) {
            d2 = na1 + nb[nt][0] - 2.0f * a4[2];
            u  = 1.0f - d2 * (1.0f / 128.0f);
            out[(size_t)tb * S_LEN + sb] = u * u * u;
        }
        if ((unsigned)(sb - 1) < S_LEN) {
            d2 = na1 + nb[nt][1] - 2.0f * a4[3];
            u  = 1.0f - d2 * (1.0f / 128.0f);
            out[(size_t)tb * S_LEN + sb - 1] = u * u * u;
        }
    }
}

extern "C" void kernel_launch(void* const* d_in, const int* in_sizes, int n_in,
                              void* d_out, int out_size)
{
    const float* x    = (const float*)d_in[0];   // (1, 2048, 1, 128) fp32
    const float* init = (const float*)d_in[1];   // (512, 128) fp32
    float* out = (float*)d_out;                  // (1, 2048, 512) fp32

    cudaFuncSetAttribute(mmd_mma_kernel,
                         cudaFuncAttributeMaxDynamicSharedMemorySize, SMEM_TOTAL);

    prep_kernel<<<NROWS / 8, NTHR>>>(x, init);   // 320 CTAs
    dim3 grid(NKT, T_LEN / BT);                  // (9, 64) = 576 CTAs, 4/SM
    mmd_mma_kernel<<<grid, NTHR, SMEM_TOTAL>>>(out);
}